// round 10
// baseline (speedup 1.0000x reference)
#include <cuda_runtime.h>
#include <cuda_bf16.h>
#include <float.h>

#define NN 100000
#define NE 1600000
#define DIM 32
#define NEG_SLOPE 0.2f

// -------- static device scratch (16B aligned for float4 access) --------
// Invariant: g_deg == 0 and g_tstat == 0 at every kernel_launch entry:
// zero at module load, re-zeroed by k_attn (deg) and k_hist (tstat) each call.
__device__ int   g_deg[NN];
__device__ int   g_cursor[NN];
__device__ int   g_rowptr[NN + 1];
__device__ int   g_tstat[128];                     // decoupled-lookback status
__device__ int   g_csrc[NE];                       // src ids grouped by dst (CSR)
__device__ float g_Dinv[NN];
__device__ __align__(16) float g_A[NN * DIM];      // pass-1 agg input (u*Dinv)
__device__ __align__(16) float g_A2[NN * DIM];     // pass-2 agg input (X1*Dinv)
__device__ __align__(16) float g_X1[NN * DIM];
__device__ __align__(16) float g_FS[NN * DIM];     // fsrc
__device__ __align__(16) float g_FD[NN * DIM];     // fdst

// ---------------------------------------------------------------------
// hist: count in-degrees; also reset lookback status for this call's scan.
__global__ void k_hist(const int* __restrict__ edst, int e) {
    int i = blockIdx.x * blockDim.x + threadIdx.x;
    if (i < 128) g_tstat[i] = 0;
    if (i < e) atomicAdd(&g_deg[edst[i]], 1);
}

// Single-pass decoupled-lookback exclusive scan of g_deg (1024 elems/block).
// Also writes rowptr, cursor, Dinv, and A = u * Dinv.
__global__ void k_scan(const float* __restrict__ u, int n) {
    __shared__ int shw[8];
    __shared__ int s_prefix;
    __shared__ float sdinv[1024];
    int bid = blockIdx.x, t = threadIdx.x;
    int base = bid * 1024;
    int lane = t & 31, w5 = t >> 5;

    int local[4];
    int tsum = 0;
#pragma unroll
    for (int k = 0; k < 4; k++) {
        int i = base + t * 4 + k;
        local[k] = (i < n) ? g_deg[i] : 0;
        tsum += local[k];
    }
    int x = tsum;
#pragma unroll
    for (int off = 1; off < 32; off <<= 1) {
        int y = __shfl_up_sync(0xffffffffu, x, off);
        if (lane >= off) x += y;
    }
    if (lane == 31) shw[w5] = x;
    __syncthreads();
    if (w5 == 0) {
        int s = (lane < 8) ? shw[lane] : 0;
#pragma unroll
        for (int off = 1; off < 8; off <<= 1) {
            int y = __shfl_up_sync(0xffffffffu, s, off);
            if (lane >= off) s += y;
        }
        if (lane < 8) shw[lane] = s;
    }
    __syncthreads();
    int incl = x + (w5 > 0 ? shw[w5 - 1] : 0);
    int btotal = shw[7];

    if (t == 0) {
        volatile int* st = (volatile int*)g_tstat;
        int ex = 0;
        if (bid == 0) {
            st[0] = 2 | (btotal << 2);
        } else {
            st[bid] = 1 | (btotal << 2);
            int p = bid - 1;
            while (true) {
                int s = st[p];
                if ((s & 3) == 0) continue;
                ex += (s >> 2);
                if ((s & 3) == 2) break;
                p--;
            }
            st[bid] = 2 | ((ex + btotal) << 2);
        }
        s_prefix = ex;
        if (bid == (int)gridDim.x - 1) g_rowptr[n] = ex + btotal;
    }
    __syncthreads();

    int excl = s_prefix + incl - tsum;
#pragma unroll
    for (int k = 0; k < 4; k++) {
        int i = base + t * 4 + k;
        if (i < n) {
            g_rowptr[i] = excl;
            g_cursor[i] = excl;
            float dg = (float)local[k];
            float d = rsqrtf(dg < 1.0f ? 1.0f : dg);
            g_Dinv[i] = d;
            sdinv[t * 4 + k] = d;
        }
        excl += local[k];
    }
    __syncthreads();

    int nnode = n - base; if (nnode > 1024) nnode = 1024;
    const float4* u4 = (const float4*)u + (size_t)base * 8;
    float4* A4 = (float4*)g_A + (size_t)base * 8;
    for (int j = t; j < nnode * 8; j += 256) {
        float d = sdinv[j >> 3];
        float4 v = u4[j];
        v.x *= d; v.y *= d; v.z *= d; v.w *= d;
        A4[j] = v;
    }
}

__global__ void k_scatter(const int* __restrict__ esrc, const int* __restrict__ edst, int e) {
    int i = blockIdx.x * blockDim.x + threadIdx.x;
    if (i < e) {
        int p = atomicAdd(&g_cursor[edst[i]], 1);
        g_csrc[p] = esrc[i];
    }
}

// agg pass 1 fused with cheb1. Warp per node; 4 groups of 8 lanes, group =
// edge. Counted for-loop unrolled 2x with independent accumulators -> 8
// independent gathers in flight per warp (MLP up from 4).
__global__ void k_aggcheb(const float* __restrict__ u, const float* __restrict__ lam, int n) {
    int w = (blockIdx.x * blockDim.x + threadIdx.x) >> 5;
    int lane = threadIdx.x & 31;
    if (w >= n) return;
    int grp = lane >> 3, sub = lane & 7;
    int s0 = g_rowptr[w], s1 = g_rowptr[w + 1];
    const float4* A4 = (const float4*)g_A;
    float4 acc0 = make_float4(0.f, 0.f, 0.f, 0.f);
    float4 acc1 = make_float4(0.f, 0.f, 0.f, 0.f);
    int e = s0 + grp;
    for (; e + 4 < s1; e += 8) {
        int sA = g_csrc[e];
        int sB = g_csrc[e + 4];
        float4 vA = A4[sA * 8 + sub];
        float4 vB = A4[sB * 8 + sub];
        acc0.x += vA.x; acc0.y += vA.y; acc0.z += vA.z; acc0.w += vA.w;
        acc1.x += vB.x; acc1.y += vB.y; acc1.z += vB.z; acc1.w += vB.w;
    }
    if (e < s1) {
        int sA = g_csrc[e];
        float4 vA = A4[sA * 8 + sub];
        acc0.x += vA.x; acc0.y += vA.y; acc0.z += vA.z; acc0.w += vA.w;
    }
    float4 acc;
    acc.x = acc0.x + acc1.x; acc.y = acc0.y + acc1.y;
    acc.z = acc0.z + acc1.z; acc.w = acc0.w + acc1.w;
    // all lanes reconverged: full-warp shuffles safe
#pragma unroll
    for (int off = 8; off <= 16; off <<= 1) {
        acc.x += __shfl_xor_sync(0xffffffffu, acc.x, off);
        acc.y += __shfl_xor_sync(0xffffffffu, acc.y, off);
        acc.z += __shfl_xor_sync(0xffffffffu, acc.z, off);
        acc.w += __shfl_xor_sync(0xffffffffu, acc.w, off);
    }
    if (grp == 0) {
        float d = g_Dinv[w];
        float r = 2.0f / lam[0];
        float4 uv = ((const float4*)u)[w * 8 + sub];
        float4 x1;
        x1.x = -r * (acc.x * d) + (r - 1.0f) * uv.x;
        x1.y = -r * (acc.y * d) + (r - 1.0f) * uv.y;
        x1.z = -r * (acc.z * d) + (r - 1.0f) * uv.z;
        x1.w = -r * (acc.w * d) + (r - 1.0f) * uv.w;
        ((float4*)g_X1)[w * 8 + sub] = x1;
        float4 a; a.x = x1.x * d; a.y = x1.y * d; a.z = x1.z * d; a.w = x1.w * d;
        ((float4*)g_A2)[w * 8 + sub] = a;
    }
}

// agg pass 2 fused with node GEMMs. 1024-thread blocks = 32 nodes/block.
__global__ __launch_bounds__(1024, 1)
void k_aggnode(const float* __restrict__ u, const float* __restrict__ lam,
               const float* __restrict__ Wc, const float* __restrict__ bc,
               const float* __restrict__ Ws, const float* __restrict__ bs,
               const float* __restrict__ Wd, const float* __restrict__ bd,
               int n) {
    __shared__ __align__(16) float sW1t[32 * 100];
    __shared__ __align__(16) float sW2t[32 * 36];
    __shared__ __align__(16) float sW3t[32 * 36];
    __shared__ float sb1[32], sb2[32], sb3[32];
    __shared__ __align__(16) float xsh[32][96];
    __shared__ __align__(16) float hcsh[32][32];

    int tid = threadIdx.x;
    for (int i = tid; i < 96 * 32; i += 1024) {
        int j = i >> 5, d = i & 31;
        sW1t[d * 100 + j] = Wc[i];
    }
    for (int i = tid; i < 32 * 32; i += 1024) {
        int j = i >> 5, d = i & 31;
        sW2t[d * 36 + j] = Ws[i];
        sW3t[d * 36 + j] = Wd[i];
    }
    if (tid < 32) { sb1[tid] = bc[tid]; sb2[tid] = bs[tid]; sb3[tid] = bd[tid]; }
    __syncthreads();

    int wid = tid >> 5, lane = tid & 31;
    int node = blockIdx.x * 32 + wid;
    if (node >= n) return;
    int grp = lane >> 3, sub = lane & 7;

    int s0 = g_rowptr[node], s1 = g_rowptr[node + 1];
    const float4* A4 = (const float4*)g_A2;
    float4 acc0 = make_float4(0.f, 0.f, 0.f, 0.f);
    float4 acc1 = make_float4(0.f, 0.f, 0.f, 0.f);
    int e = s0 + grp;
    for (; e + 4 < s1; e += 8) {
        int sA = g_csrc[e];
        int sB = g_csrc[e + 4];
        float4 vA = A4[sA * 8 + sub];
        float4 vB = A4[sB * 8 + sub];
        acc0.x += vA.x; acc0.y += vA.y; acc0.z += vA.z; acc0.w += vA.w;
        acc1.x += vB.x; acc1.y += vB.y; acc1.z += vB.z; acc1.w += vB.w;
    }
    if (e < s1) {
        int sA = g_csrc[e];
        float4 vA = A4[sA * 8 + sub];
        acc0.x += vA.x; acc0.y += vA.y; acc0.z += vA.z; acc0.w += vA.w;
    }
    float4 acc;
    acc.x = acc0.x + acc1.x; acc.y = acc0.y + acc1.y;
    acc.z = acc0.z + acc1.z; acc.w = acc0.w + acc1.w;
#pragma unroll
    for (int off = 8; off <= 16; off <<= 1) {
        acc.x += __shfl_xor_sync(0xffffffffu, acc.x, off);
        acc.y += __shfl_xor_sync(0xffffffffu, acc.y, off);
        acc.z += __shfl_xor_sync(0xffffffffu, acc.z, off);
        acc.w += __shfl_xor_sync(0xffffffffu, acc.w, off);
    }
    if (grp == 0) {
        float d = g_Dinv[node];
        float r = 2.0f / lam[0];
        float4 uv = ((const float4*)u)[node * 8 + sub];
        float4 x1 = ((const float4*)g_X1)[node * 8 + sub];
        float4 x2;
        x2.x = -2.0f * r * (acc.x * d) + 2.0f * (r - 1.0f) * x1.x - uv.x;
        x2.y = -2.0f * r * (acc.y * d) + 2.0f * (r - 1.0f) * x1.y - uv.y;
        x2.z = -2.0f * r * (acc.z * d) + 2.0f * (r - 1.0f) * x1.z - uv.z;
        x2.w = -2.0f * r * (acc.w * d) + 2.0f * (r - 1.0f) * x1.w - uv.w;
        ((float4*)&xsh[wid][0])[sub] = uv;
        ((float4*)&xsh[wid][32])[sub] = x1;
        ((float4*)&xsh[wid][64])[sub] = x2;
    }
    __syncwarp();

    float acc1s = sb1[lane];
    const float4* xr = (const float4*)&xsh[wid][0];
    const float4* w1 = (const float4*)&sW1t[lane * 100];
#pragma unroll
    for (int j4 = 0; j4 < 24; j4++) {
        float4 xv = xr[j4];
        float4 wv = w1[j4];
        acc1s += xv.x * wv.x + xv.y * wv.y + xv.z * wv.z + xv.w * wv.w;
    }
    float hc = fmaxf(acc1s, 0.0f);
    hcsh[wid][lane] = hc;
    __syncwarp();

    float fs = sb2[lane], fd = sb3[lane];
    const float4* hr = (const float4*)&hcsh[wid][0];
    const float4* w2 = (const float4*)&sW2t[lane * 36];
    const float4* w3 = (const float4*)&sW3t[lane * 36];
#pragma unroll
    for (int j4 = 0; j4 < 8; j4++) {
        float4 hv = hr[j4];
        float4 a2 = w2[j4];
        float4 a3 = w3[j4];
        fs += hv.x * a2.x + hv.y * a2.y + hv.z * a2.z + hv.w * a2.w;
        fd += hv.x * a3.x + hv.y * a3.y + hv.z * a3.z + hv.w * a3.w;
    }
    g_FS[node * DIM + lane] = fs;
    g_FD[node * DIM + lane] = fd;
}

// GATv2 fused edge softmax + aggregation, no max subtraction (logits O(13)
// max -> exp safe in fp32). 2x-unrolled edge loop with independent A/B
// chains. Group-mask shuffles inside the divergent loop; full mask after.
// Re-zeroes g_deg for the next call.
__global__ void k_attn(float* __restrict__ out, const float* __restrict__ attn, int n) {
    int gid = blockIdx.x * blockDim.x + threadIdx.x;
    if (gid < NN) g_deg[gid] = 0;          // restore call-entry invariant
    int w = gid >> 5;
    int lane = threadIdx.x & 31;
    if (w >= n) return;
    int grp = lane >> 3, sub = lane & 7;
    unsigned gmask = 0xffu << (grp * 8);
    int s0 = g_rowptr[w], s1 = g_rowptr[w + 1];
    const float4* FS4 = (const float4*)g_FS;
    float4 a4 = ((const float4*)attn)[sub];
    float4 fd4 = ((const float4*)g_FD)[w * 8 + sub];

    float den = 0.0f;
    float4 acc = make_float4(0.f, 0.f, 0.f, 0.f);

    int e = s0 + grp;
    for (; e + 4 < s1; e += 8) {
        int sA = g_csrc[e];
        int sB = g_csrc[e + 4];
        float4 vA = FS4[sA * 8 + sub];
        float4 vB = FS4[sB * 8 + sub];
        float4 tA, tB;
        tA.x = vA.x + fd4.x; tA.y = vA.y + fd4.y; tA.z = vA.z + fd4.z; tA.w = vA.w + fd4.w;
        tB.x = vB.x + fd4.x; tB.y = vB.y + fd4.y; tB.z = vB.z + fd4.z; tB.w = vB.w + fd4.w;
        tA.x = (tA.x > 0.f) ? tA.x : NEG_SLOPE * tA.x;
        tA.y = (tA.y > 0.f) ? tA.y : NEG_SLOPE * tA.y;
        tA.z = (tA.z > 0.f) ? tA.z : NEG_SLOPE * tA.z;
        tA.w = (tA.w > 0.f) ? tA.w : NEG_SLOPE * tA.w;
        tB.x = (tB.x > 0.f) ? tB.x : NEG_SLOPE * tB.x;
        tB.y = (tB.y > 0.f) ? tB.y : NEG_SLOPE * tB.y;
        tB.z = (tB.z > 0.f) ? tB.z : NEG_SLOPE * tB.z;
        tB.w = (tB.w > 0.f) ? tB.w : NEG_SLOPE * tB.w;
        float lA = tA.x * a4.x + tA.y * a4.y + tA.z * a4.z + tA.w * a4.w;
        float lB = tB.x * a4.x + tB.y * a4.y + tB.z * a4.z + tB.w * a4.w;
#pragma unroll
        for (int off = 1; off <= 4; off <<= 1) {
            lA += __shfl_xor_sync(gmask, lA, off);
            lB += __shfl_xor_sync(gmask, lB, off);
        }
        float pA = __expf(lA);
        float pB = __expf(lB);
        den += pA + pB;
        acc.x += pA * vA.x + pB * vB.x;
        acc.y += pA * vA.y + pB * vB.y;
        acc.z += pA * vA.z + pB * vB.z;
        acc.w += pA * vA.w + pB * vB.w;
    }
    if (e < s1) {
        int sA = g_csrc[e];
        float4 vA = FS4[sA * 8 + sub];
        float4 tA;
        tA.x = vA.x + fd4.x; tA.y = vA.y + fd4.y; tA.z = vA.z + fd4.z; tA.w = vA.w + fd4.w;
        tA.x = (tA.x > 0.f) ? tA.x : NEG_SLOPE * tA.x;
        tA.y = (tA.y > 0.f) ? tA.y : NEG_SLOPE * tA.y;
        tA.z = (tA.z > 0.f) ? tA.z : NEG_SLOPE * tA.z;
        tA.w = (tA.w > 0.f) ? tA.w : NEG_SLOPE * tA.w;
        float lA = tA.x * a4.x + tA.y * a4.y + tA.z * a4.z + tA.w * a4.w;
#pragma unroll
        for (int off = 1; off <= 4; off <<= 1)
            lA += __shfl_xor_sync(gmask, lA, off);
        float pA = __expf(lA);
        den += pA;
        acc.x += pA * vA.x; acc.y += pA * vA.y; acc.z += pA * vA.z; acc.w += pA * vA.w;
    }

    // merge the 4 group partial sums (all lanes reconverged -> full mask ok)
#pragma unroll
    for (int off = 8; off <= 16; off <<= 1) {
        den   += __shfl_xor_sync(0xffffffffu, den, off);
        acc.x += __shfl_xor_sync(0xffffffffu, acc.x, off);
        acc.y += __shfl_xor_sync(0xffffffffu, acc.y, off);
        acc.z += __shfl_xor_sync(0xffffffffu, acc.z, off);
        acc.w += __shfl_xor_sync(0xffffffffu, acc.w, off);
    }

    if (grp == 0) {
        float4 o;
        if (den > 0.0f) {
            float inv = 1.0f / den;
            o.x = acc.x * inv; o.y = acc.y * inv; o.z = acc.z * inv; o.w = acc.w * inv;
        } else {
            o = make_float4(0.f, 0.f, 0.f, 0.f);
        }
        ((float4*)out)[w * 8 + sub] = o;
    }
}

// ---------------------------------------------------------------------
extern "C" void kernel_launch(void* const* d_in, const int* in_sizes, int n_in,
                              void* d_out, int out_size) {
    const float* u     = (const float*)d_in[0];
    const float* lam   = (const float*)d_in[1];
    const int*   esrc  = (const int*)d_in[2];
    const int*   edst  = (const int*)d_in[3];
    const float* chebW = (const float*)d_in[4];
    const float* chebb = (const float*)d_in[5];
    const float* srcW  = (const float*)d_in[6];
    const float* srcb  = (const float*)d_in[7];
    const float* dstW  = (const float*)d_in[8];
    const float* dstb  = (const float*)d_in[9];
    const float* attn  = (const float*)d_in[10];
    float* out = (float*)d_out;

    int N = in_sizes[0] / DIM;
    int E = in_sizes[2];

    int tb = 256;
    int gE = (E + tb - 1) / tb;
    int nblkScan = (N + 1023) / 1024;
    int gWarp = (N * 32 + tb - 1) / tb;
    int gNode32 = (N + 31) / 32;

    k_hist<<<gE, tb>>>(edst, E);                              // 0
    k_scan<<<nblkScan, 256>>>(u, N);                          // 1
    k_scatter<<<gE, tb>>>(esrc, edst, E);                     // 2
    k_aggcheb<<<gWarp, tb>>>(u, lam, N);                      // 3  <- ncu lands here
    k_aggnode<<<gNode32, 1024>>>(u, lam, chebW, chebb,
                                 srcW, srcb, dstW, dstb, N);  // 4
    k_attn<<<gWarp, tb>>>(out, attn, N);                      // 5
}

// round 12
// speedup vs baseline: 1.0176x; 1.0176x over previous
#include <cuda_runtime.h>
#include <cuda_bf16.h>
#include <float.h>

#define NN 100000
#define NE 1600000
#define DIM 32
#define NEG_SLOPE 0.2f

// -------- static device scratch (16B aligned for float4 access) --------
// Invariant: g_deg == 0 and g_tstat == 0 at every kernel_launch entry:
// zero at module load, re-zeroed by k_attn (deg) and k_hist (tstat) each call.
__device__ int   g_deg[NN];
__device__ int   g_cursor[NN];
__device__ int   g_rowptr[NN + 1];
__device__ int   g_tstat[128];                     // decoupled-lookback status
__device__ int   g_csrc[NE];                       // src ids grouped by dst (CSR)
__device__ float g_Dinv[NN];
__device__ __align__(16) float g_A[NN * DIM];      // pass-1 agg input (u*Dinv)
__device__ __align__(16) float g_A2[NN * DIM];     // pass-2 agg input (X1*Dinv)
__device__ __align__(16) float g_X1[NN * DIM];
__device__ __align__(16) float g_FS[NN * DIM];     // fsrc
__device__ __align__(16) float g_FD[NN * DIM];     // fdst

// ---------------------------------------------------------------------
// hist: count in-degrees; also reset lookback status for this call's scan.
__global__ void k_hist(const int* __restrict__ edst, int e) {
    int i = blockIdx.x * blockDim.x + threadIdx.x;
    if (i < 128) g_tstat[i] = 0;
    if (i < e) atomicAdd(&g_deg[edst[i]], 1);
}

// Single-pass decoupled-lookback exclusive scan of g_deg (1024 elems/block).
// Also writes rowptr, cursor, Dinv, and A = u * Dinv.
__global__ void k_scan(const float* __restrict__ u, int n) {
    __shared__ int shw[8];
    __shared__ int s_prefix;
    __shared__ float sdinv[1024];
    int bid = blockIdx.x, t = threadIdx.x;
    int base = bid * 1024;
    int lane = t & 31, w5 = t >> 5;

    int local[4];
    int tsum = 0;
#pragma unroll
    for (int k = 0; k < 4; k++) {
        int i = base + t * 4 + k;
        local[k] = (i < n) ? g_deg[i] : 0;
        tsum += local[k];
    }
    int x = tsum;
#pragma unroll
    for (int off = 1; off < 32; off <<= 1) {
        int y = __shfl_up_sync(0xffffffffu, x, off);
        if (lane >= off) x += y;
    }
    if (lane == 31) shw[w5] = x;
    __syncthreads();
    if (w5 == 0) {
        int s = (lane < 8) ? shw[lane] : 0;
#pragma unroll
        for (int off = 1; off < 8; off <<= 1) {
            int y = __shfl_up_sync(0xffffffffu, s, off);
            if (lane >= off) s += y;
        }
        if (lane < 8) shw[lane] = s;
    }
    __syncthreads();
    int incl = x + (w5 > 0 ? shw[w5 - 1] : 0);
    int btotal = shw[7];

    if (t == 0) {
        volatile int* st = (volatile int*)g_tstat;
        int ex = 0;
        if (bid == 0) {
            st[0] = 2 | (btotal << 2);
        } else {
            st[bid] = 1 | (btotal << 2);
            int p = bid - 1;
            while (true) {
                int s = st[p];
                if ((s & 3) == 0) continue;
                ex += (s >> 2);
                if ((s & 3) == 2) break;
                p--;
            }
            st[bid] = 2 | ((ex + btotal) << 2);
        }
        s_prefix = ex;
        if (bid == (int)gridDim.x - 1) g_rowptr[n] = ex + btotal;
    }
    __syncthreads();

    int excl = s_prefix + incl - tsum;
#pragma unroll
    for (int k = 0; k < 4; k++) {
        int i = base + t * 4 + k;
        if (i < n) {
            g_rowptr[i] = excl;
            g_cursor[i] = excl;
            float dg = (float)local[k];
            float d = rsqrtf(dg < 1.0f ? 1.0f : dg);
            g_Dinv[i] = d;
            sdinv[t * 4 + k] = d;
        }
        excl += local[k];
    }
    __syncthreads();

    int nnode = n - base; if (nnode > 1024) nnode = 1024;
    const float4* u4 = (const float4*)u + (size_t)base * 8;
    float4* A4 = (float4*)g_A + (size_t)base * 8;
    for (int j = t; j < nnode * 8; j += 256) {
        float d = sdinv[j >> 3];
        float4 v = u4[j];
        v.x *= d; v.y *= d; v.z *= d; v.w *= d;
        A4[j] = v;
    }
}

__global__ void k_scatter(const int* __restrict__ esrc, const int* __restrict__ edst, int e) {
    int i = blockIdx.x * blockDim.x + threadIdx.x;
    if (i < e) {
        int p = atomicAdd(&g_cursor[edst[i]], 1);
        g_csrc[p] = esrc[i];
    }
}

// agg pass 1 fused with cheb1. Warp per node; 4 groups of 8 lanes, group =
// edge. Plain counted loop — measured fastest (R8: 33.2us); ptxas schedules
// this form better than manual pipelining/unrolling (R9: 38.6, R10: 36.6).
__global__ void k_aggcheb(const float* __restrict__ u, const float* __restrict__ lam, int n) {
    int w = (blockIdx.x * blockDim.x + threadIdx.x) >> 5;
    int lane = threadIdx.x & 31;
    if (w >= n) return;
    int grp = lane >> 3, sub = lane & 7;
    int s0 = g_rowptr[w], s1 = g_rowptr[w + 1];
    const float4* A4 = (const float4*)g_A;
    float4 acc = make_float4(0.f, 0.f, 0.f, 0.f);
    for (int e = s0 + grp; e < s1; e += 4) {
        int sid = g_csrc[e];
        float4 v = A4[sid * 8 + sub];
        acc.x += v.x; acc.y += v.y; acc.z += v.z; acc.w += v.w;
    }
    // all lanes reconverged: full-warp shuffles safe
#pragma unroll
    for (int off = 8; off <= 16; off <<= 1) {
        acc.x += __shfl_xor_sync(0xffffffffu, acc.x, off);
        acc.y += __shfl_xor_sync(0xffffffffu, acc.y, off);
        acc.z += __shfl_xor_sync(0xffffffffu, acc.z, off);
        acc.w += __shfl_xor_sync(0xffffffffu, acc.w, off);
    }
    if (grp == 0) {
        float d = g_Dinv[w];
        float r = 2.0f / lam[0];
        float4 uv = ((const float4*)u)[w * 8 + sub];
        float4 x1;
        x1.x = -r * (acc.x * d) + (r - 1.0f) * uv.x;
        x1.y = -r * (acc.y * d) + (r - 1.0f) * uv.y;
        x1.z = -r * (acc.z * d) + (r - 1.0f) * uv.z;
        x1.w = -r * (acc.w * d) + (r - 1.0f) * uv.w;
        ((float4*)g_X1)[w * 8 + sub] = x1;
        float4 a; a.x = x1.x * d; a.y = x1.y * d; a.z = x1.z * d; a.w = x1.w * d;
        ((float4*)g_A2)[w * 8 + sub] = a;
    }
}

// agg pass 2 fused with node GEMMs. 1024-thread blocks = 32 nodes/block.
// Plain counted gather loop (same reasoning as k_aggcheb).
__global__ __launch_bounds__(1024, 1)
void k_aggnode(const float* __restrict__ u, const float* __restrict__ lam,
               const float* __restrict__ Wc, const float* __restrict__ bc,
               const float* __restrict__ Ws, const float* __restrict__ bs,
               const float* __restrict__ Wd, const float* __restrict__ bd,
               int n) {
    __shared__ __align__(16) float sW1t[32 * 100];
    __shared__ __align__(16) float sW2t[32 * 36];
    __shared__ __align__(16) float sW3t[32 * 36];
    __shared__ float sb1[32], sb2[32], sb3[32];
    __shared__ __align__(16) float xsh[32][96];
    __shared__ __align__(16) float hcsh[32][32];

    int tid = threadIdx.x;
    for (int i = tid; i < 96 * 32; i += 1024) {
        int j = i >> 5, d = i & 31;
        sW1t[d * 100 + j] = Wc[i];
    }
    for (int i = tid; i < 32 * 32; i += 1024) {
        int j = i >> 5, d = i & 31;
        sW2t[d * 36 + j] = Ws[i];
        sW3t[d * 36 + j] = Wd[i];
    }
    if (tid < 32) { sb1[tid] = bc[tid]; sb2[tid] = bs[tid]; sb3[tid] = bd[tid]; }
    __syncthreads();

    int wid = tid >> 5, lane = tid & 31;
    int node = blockIdx.x * 32 + wid;
    if (node >= n) return;
    int grp = lane >> 3, sub = lane & 7;

    int s0 = g_rowptr[node], s1 = g_rowptr[node + 1];
    const float4* A4 = (const float4*)g_A2;
    float4 acc = make_float4(0.f, 0.f, 0.f, 0.f);
    for (int e = s0 + grp; e < s1; e += 4) {
        int sid = g_csrc[e];
        float4 v = A4[sid * 8 + sub];
        acc.x += v.x; acc.y += v.y; acc.z += v.z; acc.w += v.w;
    }
#pragma unroll
    for (int off = 8; off <= 16; off <<= 1) {
        acc.x += __shfl_xor_sync(0xffffffffu, acc.x, off);
        acc.y += __shfl_xor_sync(0xffffffffu, acc.y, off);
        acc.z += __shfl_xor_sync(0xffffffffu, acc.z, off);
        acc.w += __shfl_xor_sync(0xffffffffu, acc.w, off);
    }
    if (grp == 0) {
        float d = g_Dinv[node];
        float r = 2.0f / lam[0];
        float4 uv = ((const float4*)u)[node * 8 + sub];
        float4 x1 = ((const float4*)g_X1)[node * 8 + sub];
        float4 x2;
        x2.x = -2.0f * r * (acc.x * d) + 2.0f * (r - 1.0f) * x1.x - uv.x;
        x2.y = -2.0f * r * (acc.y * d) + 2.0f * (r - 1.0f) * x1.y - uv.y;
        x2.z = -2.0f * r * (acc.z * d) + 2.0f * (r - 1.0f) * x1.z - uv.z;
        x2.w = -2.0f * r * (acc.w * d) + 2.0f * (r - 1.0f) * x1.w - uv.w;
        ((float4*)&xsh[wid][0])[sub] = uv;
        ((float4*)&xsh[wid][32])[sub] = x1;
        ((float4*)&xsh[wid][64])[sub] = x2;
    }
    __syncwarp();

    float acc1s = sb1[lane];
    const float4* xr = (const float4*)&xsh[wid][0];
    const float4* w1 = (const float4*)&sW1t[lane * 100];
#pragma unroll
    for (int j4 = 0; j4 < 24; j4++) {
        float4 xv = xr[j4];
        float4 wv = w1[j4];
        acc1s += xv.x * wv.x + xv.y * wv.y + xv.z * wv.z + xv.w * wv.w;
    }
    float hc = fmaxf(acc1s, 0.0f);
    hcsh[wid][lane] = hc;
    __syncwarp();

    float fs = sb2[lane], fd = sb3[lane];
    const float4* hr = (const float4*)&hcsh[wid][0];
    const float4* w2 = (const float4*)&sW2t[lane * 36];
    const float4* w3 = (const float4*)&sW3t[lane * 36];
#pragma unroll
    for (int j4 = 0; j4 < 8; j4++) {
        float4 hv = hr[j4];
        float4 a2 = w2[j4];
        float4 a3 = w3[j4];
        fs += hv.x * a2.x + hv.y * a2.y + hv.z * a2.z + hv.w * a2.w;
        fd += hv.x * a3.x + hv.y * a3.y + hv.z * a3.z + hv.w * a3.w;
    }
    g_FS[node * DIM + lane] = fs;
    g_FD[node * DIM + lane] = fd;
}

// GATv2 fused edge softmax + aggregation, no max subtraction (logits bounded
// ~13 -> exp safe in fp32). Plain loop (R9 form — measured best). Group-mask
// shuffles inside the divergent loop; full mask after reconvergence.
// Re-zeroes g_deg for the next call.
__global__ void k_attn(float* __restrict__ out, const float* __restrict__ attn, int n) {
    int gid = blockIdx.x * blockDim.x + threadIdx.x;
    if (gid < NN) g_deg[gid] = 0;          // restore call-entry invariant
    int w = gid >> 5;
    int lane = threadIdx.x & 31;
    if (w >= n) return;
    int grp = lane >> 3, sub = lane & 7;
    unsigned gmask = 0xffu << (grp * 8);
    int s0 = g_rowptr[w], s1 = g_rowptr[w + 1];
    const float4* FS4 = (const float4*)g_FS;
    float4 a4 = ((const float4*)attn)[sub];
    float4 fd4 = ((const float4*)g_FD)[w * 8 + sub];

    float den = 0.0f;
    float4 acc = make_float4(0.f, 0.f, 0.f, 0.f);

    for (int e = s0 + grp; e < s1; e += 4) {
        int sid = g_csrc[e];
        float4 v = FS4[sid * 8 + sub];
        float4 t;
        t.x = v.x + fd4.x; t.y = v.y + fd4.y; t.z = v.z + fd4.z; t.w = v.w + fd4.w;
        t.x = (t.x > 0.f) ? t.x : NEG_SLOPE * t.x;
        t.y = (t.y > 0.f) ? t.y : NEG_SLOPE * t.y;
        t.z = (t.z > 0.f) ? t.z : NEG_SLOPE * t.z;
        t.w = (t.w > 0.f) ? t.w : NEG_SLOPE * t.w;
        float l = t.x * a4.x + t.y * a4.y + t.z * a4.z + t.w * a4.w;
#pragma unroll
        for (int off = 1; off <= 4; off <<= 1)
            l += __shfl_xor_sync(gmask, l, off);   // group-local, converged
        float p = __expf(l);
        den += p;
        acc.x += p * v.x; acc.y += p * v.y; acc.z += p * v.z; acc.w += p * v.w;
    }

    // merge the 4 group partial sums (all lanes reconverged -> full mask ok)
#pragma unroll
    for (int off = 8; off <= 16; off <<= 1) {
        den   += __shfl_xor_sync(0xffffffffu, den, off);
        acc.x += __shfl_xor_sync(0xffffffffu, acc.x, off);
        acc.y += __shfl_xor_sync(0xffffffffu, acc.y, off);
        acc.z += __shfl_xor_sync(0xffffffffu, acc.z, off);
        acc.w += __shfl_xor_sync(0xffffffffu, acc.w, off);
    }

    if (grp == 0) {
        float4 o;
        if (den > 0.0f) {
            float inv = 1.0f / den;
            o.x = acc.x * inv; o.y = acc.y * inv; o.z = acc.z * inv; o.w = acc.w * inv;
        } else {
            o = make_float4(0.f, 0.f, 0.f, 0.f);
        }
        ((float4*)out)[w * 8 + sub] = o;
    }
}

// ---------------------------------------------------------------------
extern "C" void kernel_launch(void* const* d_in, const int* in_sizes, int n_in,
                              void* d_out, int out_size) {
    const float* u     = (const float*)d_in[0];
    const float* lam   = (const float*)d_in[1];
    const int*   esrc  = (const int*)d_in[2];
    const int*   edst  = (const int*)d_in[3];
    const float* chebW = (const float*)d_in[4];
    const float* chebb = (const float*)d_in[5];
    const float* srcW  = (const float*)d_in[6];
    const float* srcb  = (const float*)d_in[7];
    const float* dstW  = (const float*)d_in[8];
    const float* dstb  = (const float*)d_in[9];
    const float* attn  = (const float*)d_in[10];
    float* out = (float*)d_out;

    int N = in_sizes[0] / DIM;
    int E = in_sizes[2];

    int tb = 256;
    int gE = (E + tb - 1) / tb;
    int nblkScan = (N + 1023) / 1024;
    int gWarp = (N * 32 + tb - 1) / tb;
    int gNode32 = (N + 31) / 32;

    k_hist<<<gE, tb>>>(edst, E);                              // 0
    k_scan<<<nblkScan, 256>>>(u, N);                          // 1
    k_scatter<<<gE, tb>>>(esrc, edst, E);                     // 2
    k_aggcheb<<<gWarp, tb>>>(u, lam, N);                      // 3  <- ncu lands here
    k_aggnode<<<gNode32, 1024>>>(u, lam, chebW, chebb,
                                 srcW, srcb, dstW, dstb, N);  // 4
    k_attn<<<gWarp, tb>>>(out, attn, N);                      // 5
}